// round 1
// baseline (speedup 1.0000x reference)
#include <cuda_runtime.h>
#include <math.h>

#define Bb   8
#define Cc   256
#define Hh   64
#define Ww   64
#define Gg   16
#define Dd   16
#define Kk   7
#define Pp   3
#define CRr  64
#define KKG  784
#define HW   4096
#define EPSf 1e-5f

// ---------------- scratch (device globals — no allocation at runtime) --------
__device__ float g_wr[CRr * Cc];     // folded reduce weights (weight-norm * BN scale)
__device__ float g_br[CRr];          // folded reduce bias
__device__ float g_ws[KKG * CRr];    // weight-normed span weights
__device__ float g_bsp[KKG];         // span bias
__device__ float g_r[Bb * CRr * HW];     // reduce output   (8 MB)
__device__ float g_ker[(size_t)Bb * KKG * HW]; // span output (103 MB)

// ---------------- weight preparation -----------------------------------------
__global__ void prep_weights(const float* __restrict__ v_reduce,
                             const float* __restrict__ g_reduce,
                             const float* __restrict__ b_reduce,
                             const float* __restrict__ bn_gamma,
                             const float* __restrict__ bn_beta,
                             const float* __restrict__ bn_mean,
                             const float* __restrict__ bn_var,
                             const float* __restrict__ v_span,
                             const float* __restrict__ g_span,
                             const float* __restrict__ b_span) {
    __shared__ float red[64];
    int row = blockIdx.x;
    int t = threadIdx.x;
    if (row < CRr) {
        float s = 0.f;
        for (int c = t; c < Cc; c += 64) {
            float v = v_reduce[row * Cc + c];
            s += v * v;
        }
        red[t] = s; __syncthreads();
        for (int off = 32; off > 0; off >>= 1) {
            if (t < off) red[t] += red[t + off];
            __syncthreads();
        }
        float nrm   = sqrtf(red[0]);
        float scale = bn_gamma[row] * rsqrtf(bn_var[row] + EPSf);
        float wmul  = g_reduce[row] / nrm * scale;
        for (int c = t; c < Cc; c += 64)
            g_wr[row * Cc + c] = v_reduce[row * Cc + c] * wmul;
        if (t == 0)
            g_br[row] = (b_reduce[row] - bn_mean[row]) * scale + bn_beta[row];
    } else {
        int o = row - CRr;
        float s = 0.f;
        for (int c = t; c < CRr; c += 64) {
            float v = v_span[o * CRr + c];
            s += v * v;
        }
        red[t] = s; __syncthreads();
        for (int off = 32; off > 0; off >>= 1) {
            if (t < off) red[t] += red[t + off];
            __syncthreads();
        }
        float wmul = g_span[o] / sqrtf(red[0]);
        for (int c = t; c < CRr; c += 64)
            g_ws[o * CRr + c] = v_span[o * CRr + c] * wmul;
        if (t == 0) g_bsp[o] = b_span[o];
    }
}

// ---------------- tiled SGEMM: Y[b,m,n] = sum_k W[m,k] X[b,k,n] + bias[m] ----
// block tile 64(m) x 64(n), K-step 16, 256 threads, 4x4 register tile
template <int MTOT, int KD, bool RELU>
__global__ void gemm_bias(const float* __restrict__ Wt, const float* __restrict__ bias,
                          const float* __restrict__ X, float* __restrict__ Y) {
    __shared__ float As[16][64];   // [k][m]
    __shared__ float Bs[16][64];   // [k][n]
    int b  = blockIdx.z;
    int m0 = blockIdx.y * 64;
    int n0 = blockIdx.x * 64;
    int tid = threadIdx.x;
    int tx = tid & 15, ty = tid >> 4;
    const float* Xb = X + (size_t)b * KD * HW;

    float acc[4][4] = {};
    for (int k0 = 0; k0 < KD; k0 += 16) {
        // A tile: W[m0+lm][k0+lk..+3] -> As[k][m]
        {
            int lm = tid >> 2;
            int lk = (tid & 3) * 4;
            int gm = m0 + lm;
#pragma unroll
            for (int i = 0; i < 4; i++) {
                float v = 0.f;
                if (gm < MTOT) v = Wt[(size_t)gm * KD + k0 + lk + i];
                As[lk + i][lm] = v;
            }
        }
        // B tile: X[k0+lk][n0+ln..+3] -> Bs[k][n]
        {
            int lk = tid >> 4;
            int ln = (tid & 15) * 4;
            float4 v = *(const float4*)(Xb + (size_t)(k0 + lk) * HW + n0 + ln);
            *(float4*)&Bs[lk][ln] = v;
        }
        __syncthreads();
#pragma unroll
        for (int kk = 0; kk < 16; kk++) {
            float4 a = *(const float4*)&As[kk][ty * 4];
            float4 bv = *(const float4*)&Bs[kk][tx * 4];
            float av[4] = {a.x, a.y, a.z, a.w};
            float bw[4] = {bv.x, bv.y, bv.z, bv.w};
#pragma unroll
            for (int i = 0; i < 4; i++)
#pragma unroll
                for (int j = 0; j < 4; j++)
                    acc[i][j] += av[i] * bw[j];
        }
        __syncthreads();
    }
#pragma unroll
    for (int i = 0; i < 4; i++) {
        int gm = m0 + ty * 4 + i;
        if (gm < MTOT) {
            float bi = bias[gm];
            float4 o;
            o.x = acc[i][0] + bi;
            o.y = acc[i][1] + bi;
            o.z = acc[i][2] + bi;
            o.w = acc[i][3] + bi;
            if (RELU) {
                o.x = fmaxf(o.x, 0.f); o.y = fmaxf(o.y, 0.f);
                o.z = fmaxf(o.z, 0.f); o.w = fmaxf(o.w, 0.f);
            }
            *(float4*)(Y + ((size_t)b * MTOT + gm) * HW + n0 + tx * 4) = o;
        }
    }
}

// ---------------- involution: 16x16 pixel tile, all 16 d per thread ----------
#define TS   16
#define XD   22          // 16 + 2*3 halo
#define XSTR 20          // padded d-stride (16 -> 20) to spread smem banks
__global__ __launch_bounds__(256) void involution_kernel(
        const float* __restrict__ x, const float* __restrict__ ker,
        float* __restrict__ out) {
    __shared__ float xs[XD * XD * XSTR];   // 38,720 B
    int bz = blockIdx.z;             // b*G + g
    int b = bz >> 4, g = bz & 15;
    int h0 = blockIdx.y * TS;
    int w0 = blockIdx.x * TS;
    int tid = threadIdx.x;

    const float* xbg = x + ((size_t)(b * Cc + g * Dd)) * HW;
    for (int idx = tid; idx < Dd * XD * XD; idx += 256) {
        int d  = idx / (XD * XD);
        int r  = idx - d * (XD * XD);
        int yy = r / XD;
        int xx = r - yy * XD;
        int gy = h0 + yy - Pp;
        int gx = w0 + xx - Pp;
        float v = 0.f;
        if (gy >= 0 && gy < Hh && gx >= 0 && gx < Ww)
            v = xbg[(size_t)d * HW + gy * Ww + gx];
        xs[(yy * XD + xx) * XSTR + d] = v;
    }
    __syncthreads();

    int tx = tid & 15, ty = tid >> 4;
    int h = h0 + ty, w = w0 + tx;
    // span channel layout: o = (ki*7+kj)*G + g
    const float* kbase = ker + ((size_t)b * KKG + g) * HW + h * Ww + w;

    float acc[16] = {};
#pragma unroll
    for (int ki = 0; ki < 7; ki++) {
        float kr[7];
#pragma unroll
        for (int kj = 0; kj < 7; kj++)
            kr[kj] = kbase[(size_t)((ki * 7 + kj) * Gg) * HW];
#pragma unroll
        for (int kj = 0; kj < 7; kj++) {
            float kv = kr[kj];
            const float* p = &xs[((ty + ki) * XD + (tx + kj)) * XSTR];
#pragma unroll
            for (int dc = 0; dc < 4; dc++) {
                float4 v = *(const float4*)(p + dc * 4);
                acc[dc * 4 + 0] += v.x * kv;
                acc[dc * 4 + 1] += v.y * kv;
                acc[dc * 4 + 2] += v.z * kv;
                acc[dc * 4 + 3] += v.w * kv;
            }
        }
    }

    float* op = out + ((size_t)(b * Cc + g * Dd)) * HW + h * Ww + w;
#pragma unroll
    for (int d = 0; d < 16; d++)
        op[(size_t)d * HW] = acc[d];
}

// ---------------- launcher ---------------------------------------------------
extern "C" void kernel_launch(void* const* d_in, const int* in_sizes, int n_in,
                              void* d_out, int out_size) {
    const float* x        = (const float*)d_in[0];
    const float* v_reduce = (const float*)d_in[1];
    const float* g_reduce = (const float*)d_in[2];
    const float* b_reduce = (const float*)d_in[3];
    const float* bn_gamma = (const float*)d_in[4];
    const float* bn_beta  = (const float*)d_in[5];
    const float* bn_mean  = (const float*)d_in[6];
    const float* bn_var   = (const float*)d_in[7];
    const float* v_span   = (const float*)d_in[8];
    const float* g_span   = (const float*)d_in[9];
    const float* b_span   = (const float*)d_in[10];
    float* out = (float*)d_out;

    float *wr, *br, *ws, *bsp, *r, *ker;
    cudaGetSymbolAddress((void**)&wr,  g_wr);
    cudaGetSymbolAddress((void**)&br,  g_br);
    cudaGetSymbolAddress((void**)&ws,  g_ws);
    cudaGetSymbolAddress((void**)&bsp, g_bsp);
    cudaGetSymbolAddress((void**)&r,   g_r);
    cudaGetSymbolAddress((void**)&ker, g_ker);

    prep_weights<<<CRr + KKG, 64>>>(v_reduce, g_reduce, b_reduce,
                                    bn_gamma, bn_beta, bn_mean, bn_var,
                                    v_span, g_span, b_span);

    // reduce: M=64, K=256, relu
    gemm_bias<CRr, Cc, true><<<dim3(HW / 64, 1, Bb), 256>>>(wr, br, x, r);

    // span: M=784, K=64
    gemm_bias<KKG, CRr, false><<<dim3(HW / 64, (KKG + 63) / 64, Bb), 256>>>(ws, bsp, r, ker);

    // involution
    involution_kernel<<<dim3(Ww / TS, Hh / TS, Bb * Gg), 256>>>(x, ker, out);
}

// round 2
// speedup vs baseline: 1.3150x; 1.3150x over previous
#include <cuda_runtime.h>
#include <math.h>

#define Bb   8
#define Cc   256
#define Hh   64
#define Ww   64
#define Gg   16
#define Dd   16
#define Pp   3
#define CRr  64
#define NT   49          // 7*7 taps
#define KKG  784
#define HW   4096
#define EPSf 1e-5f

// ---------------- scratch (device globals) -----------------------------------
__device__ float g_wr[CRr * Cc];        // folded reduce weights
__device__ float g_br[CRr];             // folded reduce bias
__device__ float g_wsT[Gg * CRr * NT];  // span weights as [g][c][t]
__device__ float g_bsp[KKG];            // span bias, indexed o = t*16+g
__device__ float g_r[Bb * CRr * HW];    // reduce output (8 MB)

// ---------------- weight preparation -----------------------------------------
__global__ void prep_weights(const float* __restrict__ v_reduce,
                             const float* __restrict__ g_reduce,
                             const float* __restrict__ b_reduce,
                             const float* __restrict__ bn_gamma,
                             const float* __restrict__ bn_beta,
                             const float* __restrict__ bn_mean,
                             const float* __restrict__ bn_var,
                             const float* __restrict__ v_span,
                             const float* __restrict__ g_span,
                             const float* __restrict__ b_span) {
    __shared__ float red[64];
    int row = blockIdx.x;
    int t = threadIdx.x;
    if (row < CRr) {
        float s = 0.f;
        for (int c = t; c < Cc; c += 64) {
            float v = v_reduce[row * Cc + c];
            s += v * v;
        }
        red[t] = s; __syncthreads();
        for (int off = 32; off > 0; off >>= 1) {
            if (t < off) red[t] += red[t + off];
            __syncthreads();
        }
        float nrm   = sqrtf(red[0]);
        float scale = bn_gamma[row] * rsqrtf(bn_var[row] + EPSf);
        float wmul  = g_reduce[row] / nrm * scale;
        for (int c = t; c < Cc; c += 64)
            g_wr[row * Cc + c] = v_reduce[row * Cc + c] * wmul;
        if (t == 0)
            g_br[row] = (b_reduce[row] - bn_mean[row]) * scale + bn_beta[row];
    } else {
        int o = row - CRr;            // 0..783,  o = tap*16 + g
        int tap = o >> 4;
        int gq  = o & 15;
        float s = 0.f;
        for (int c = t; c < CRr; c += 64) {
            float v = v_span[o * CRr + c];
            s += v * v;
        }
        red[t] = s; __syncthreads();
        for (int off = 32; off > 0; off >>= 1) {
            if (t < off) red[t] += red[t + off];
            __syncthreads();
        }
        float wmul = g_span[o] / sqrtf(red[0]);
        for (int c = t; c < CRr; c += 64)
            g_wsT[(gq * CRr + c) * NT + tap] = v_span[o * CRr + c] * wmul;
        if (t == 0) g_bsp[o] = b_span[o];
    }
}

// ---------------- reduce SGEMM: r[b,m,n] = relu(sum_k W[m,k] X[b,k,n] + bias) -
template <int MTOT, int KD, bool RELU>
__global__ void gemm_bias(const float* __restrict__ Wt, const float* __restrict__ bias,
                          const float* __restrict__ X, float* __restrict__ Y) {
    __shared__ float As[16][64];
    __shared__ float Bs[16][64];
    int b  = blockIdx.z;
    int m0 = blockIdx.y * 64;
    int n0 = blockIdx.x * 64;
    int tid = threadIdx.x;
    int tx = tid & 15, ty = tid >> 4;
    const float* Xb = X + (size_t)b * KD * HW;

    float acc[4][4] = {};
    for (int k0 = 0; k0 < KD; k0 += 16) {
        {
            int lm = tid >> 2;
            int lk = (tid & 3) * 4;
            int gm = m0 + lm;
#pragma unroll
            for (int i = 0; i < 4; i++) {
                float v = 0.f;
                if (gm < MTOT) v = Wt[(size_t)gm * KD + k0 + lk + i];
                As[lk + i][lm] = v;
            }
        }
        {
            int lk = tid >> 4;
            int ln = (tid & 15) * 4;
            float4 v = *(const float4*)(Xb + (size_t)(k0 + lk) * HW + n0 + ln);
            *(float4*)&Bs[lk][ln] = v;
        }
        __syncthreads();
#pragma unroll
        for (int kk = 0; kk < 16; kk++) {
            float4 a = *(const float4*)&As[kk][ty * 4];
            float4 bv = *(const float4*)&Bs[kk][tx * 4];
            float av[4] = {a.x, a.y, a.z, a.w};
            float bw[4] = {bv.x, bv.y, bv.z, bv.w};
#pragma unroll
            for (int i = 0; i < 4; i++)
#pragma unroll
                for (int j = 0; j < 4; j++)
                    acc[i][j] += av[i] * bw[j];
        }
        __syncthreads();
    }
#pragma unroll
    for (int i = 0; i < 4; i++) {
        int gm = m0 + ty * 4 + i;
        if (gm < MTOT) {
            float bi = bias[gm];
            float4 o;
            o.x = acc[i][0] + bi;
            o.y = acc[i][1] + bi;
            o.z = acc[i][2] + bi;
            o.w = acc[i][3] + bi;
            if (RELU) {
                o.x = fmaxf(o.x, 0.f); o.y = fmaxf(o.y, 0.f);
                o.z = fmaxf(o.z, 0.f); o.w = fmaxf(o.w, 0.f);
            }
            *(float4*)(Y + ((size_t)b * MTOT + gm) * HW + n0 + tx * 4) = o;
        }
    }
}

// ---------------- fused span + involution -------------------------------------
#define TS   16
#define XD   22
#define XSTR 20
// smem layout (float offsets)
#define OFF_KER 0                              // 49*256          = 12544
#define OFF_RS  (OFF_KER + NT * 256)           // 64*256          = 16384
#define OFF_XS  (OFF_RS + CRr * 256)           // 484*20          =  9680
#define OFF_WS  (OFF_XS + XD * XD * XSTR)      // 64*56           =  3584
#define OFF_BS  (OFF_WS + CRr * 56)            // 56
#define SMEM_FL (OFF_BS + 56)                  // 42248 floats = 168,992 B

extern __shared__ float sm_f[];

__global__ __launch_bounds__(256, 1) void fused_kernel(
        const float* __restrict__ x, const float* __restrict__ r,
        float* __restrict__ out) {
    int tid = threadIdx.x;
    int bz = blockIdx.z;
    int b = bz >> 4, g = bz & 15;
    int h0 = blockIdx.y * TS, w0 = blockIdx.x * TS;

    float* ker_s = sm_f + OFF_KER;   // [tap][pix] stride 256
    float* rs    = sm_f + OFF_RS;    // [c][pix]   stride 256
    float* xs    = sm_f + OFF_XS;    // [pos][d]   stride 20
    float* ws_s  = sm_f + OFF_WS;    // [k][m]     stride 56
    float* bs_s  = sm_f + OFF_BS;    // [m]

    // ---- loads -------------------------------------------------------------
    const float* rb = r + (size_t)b * CRr * HW;
    for (int i4 = tid; i4 < CRr * 64; i4 += 256) {      // 64 float4 per channel
        int c = i4 >> 6, rem = i4 & 63;
        int y = rem >> 2, x4 = (rem & 3) << 2;
        float4 v = *(const float4*)(rb + (size_t)c * HW + (h0 + y) * Ww + w0 + x4);
        *(float4*)(rs + c * 256 + y * 16 + x4) = v;
    }
    for (int i = tid; i < CRr * 56; i += 256) {
        int k = i / 56, m = i - k * 56;
        ws_s[i] = (m < NT) ? g_wsT[(g * CRr + k) * NT + m] : 0.f;
    }
    if (tid < 56) bs_s[tid] = (tid < NT) ? g_bsp[tid * Gg + g] : 0.f;

    const float* xbg = x + (size_t)(b * Cc + g * Dd) * HW;
    for (int idx = tid; idx < Dd * XD * XD; idx += 256) {
        int d  = idx / (XD * XD);
        int rr = idx - d * (XD * XD);
        int yy = rr / XD;
        int xx = rr - yy * XD;
        int gy = h0 + yy - Pp;
        int gx = w0 + xx - Pp;
        float v = 0.f;
        if (gy >= 0 && gy < Hh && gx >= 0 && gx < Ww)
            v = xbg[(size_t)d * HW + gy * Ww + gx];
        xs[(yy * XD + xx) * XSTR + d] = v;
    }
    __syncthreads();

    // ---- phase 1: ker_s[t][pix] = sum_k ws[t][k] * rs[k][pix] + bias[t] -----
    {
        int tx = tid & 31;         // pixel lane
        int my = tid >> 5;         // warp -> 7 taps
        float acc[7][8];
#pragma unroll
        for (int i = 0; i < 7; i++) {
            float bi = bs_s[my * 7 + i];
#pragma unroll
            for (int j = 0; j < 8; j++) acc[i][j] = bi;
        }
        for (int k = 0; k < CRr; k++) {
            float a[7];
#pragma unroll
            for (int i = 0; i < 7; i++) a[i] = ws_s[k * 56 + my * 7 + i];
            float4 b0 = *(const float4*)(rs + k * 256 + tx * 4);
            float4 b1 = *(const float4*)(rs + k * 256 + 128 + tx * 4);
            float bv[8] = {b0.x, b0.y, b0.z, b0.w, b1.x, b1.y, b1.z, b1.w};
#pragma unroll
            for (int i = 0; i < 7; i++)
#pragma unroll
                for (int j = 0; j < 8; j++)
                    acc[i][j] += a[i] * bv[j];
        }
#pragma unroll
        for (int i = 0; i < 7; i++) {
            int m = my * 7 + i;
            if (m < NT) {
                *(float4*)(ker_s + m * 256 + tx * 4) =
                    make_float4(acc[i][0], acc[i][1], acc[i][2], acc[i][3]);
                *(float4*)(ker_s + m * 256 + 128 + tx * 4) =
                    make_float4(acc[i][4], acc[i][5], acc[i][6], acc[i][7]);
            }
        }
    }
    __syncthreads();

    // ---- phase 2: involution -------------------------------------------------
    {
        int pg = tid >> 2;           // 64 pixel groups (4 consecutive pixels)
        int dq = tid & 3;            // d quad
        int p0 = pg * 4;
        int y  = p0 >> 4;
        int x0 = p0 & 15;
        int d0 = dq * 4;

        float acc[4][4];             // [dd][px]
#pragma unroll
        for (int dd = 0; dd < 4; dd++)
#pragma unroll
            for (int px = 0; px < 4; px++) acc[dd][px] = 0.f;

#pragma unroll
        for (int ki = 0; ki < 7; ki++) {
            const float* xrow = xs + ((y + ki) * XD + x0) * XSTR + d0;
            float cur[4][4];         // rotating window of 4 positions x 4 d
#pragma unroll
            for (int p = 0; p < 3; p++) {
                float4 v = *(const float4*)(xrow + p * XSTR);
                cur[p][0] = v.x; cur[p][1] = v.y; cur[p][2] = v.z; cur[p][3] = v.w;
            }
#pragma unroll
            for (int kj = 0; kj < 7; kj++) {
                {
                    float4 v = *(const float4*)(xrow + (kj + 3) * XSTR);
                    int s = (kj + 3) & 3;
                    cur[s][0] = v.x; cur[s][1] = v.y; cur[s][2] = v.z; cur[s][3] = v.w;
                }
                float4 kv = *(const float4*)(ker_s + (ki * 7 + kj) * 256 + p0);
                float kvv[4] = {kv.x, kv.y, kv.z, kv.w};
#pragma unroll
                for (int px = 0; px < 4; px++) {
                    int s = (kj + px) & 3;
#pragma unroll
                    for (int dd = 0; dd < 4; dd++)
                        acc[dd][px] += cur[s][dd] * kvv[px];
                }
            }
        }

        float* ob = out + (size_t)(b * Cc + g * Dd + d0) * HW + (h0 + y) * Ww + w0 + x0;
#pragma unroll
        for (int dd = 0; dd < 4; dd++) {
            float4 o = make_float4(acc[dd][0], acc[dd][1], acc[dd][2], acc[dd][3]);
            *(float4*)(ob + (size_t)dd * HW) = o;
        }
    }
}

// ---------------- launcher ------------------------------------------------------
extern "C" void kernel_launch(void* const* d_in, const int* in_sizes, int n_in,
                              void* d_out, int out_size) {
    const float* x        = (const float*)d_in[0];
    const float* v_reduce = (const float*)d_in[1];
    const float* g_reduce = (const float*)d_in[2];
    const float* b_reduce = (const float*)d_in[3];
    const float* bn_gamma = (const float*)d_in[4];
    const float* bn_beta  = (const float*)d_in[5];
    const float* bn_mean  = (const float*)d_in[6];
    const float* bn_var   = (const float*)d_in[7];
    const float* v_span   = (const float*)d_in[8];
    const float* g_span   = (const float*)d_in[9];
    const float* b_span   = (const float*)d_in[10];
    float* out = (float*)d_out;

    float *wr, *br, *r;
    cudaGetSymbolAddress((void**)&wr, g_wr);
    cudaGetSymbolAddress((void**)&br, g_br);
    cudaGetSymbolAddress((void**)&r,  g_r);

    static bool attr_set = false;
    if (!attr_set) {
        cudaFuncSetAttribute(fused_kernel,
                             cudaFuncAttributeMaxDynamicSharedMemorySize,
                             SMEM_FL * sizeof(float));
        attr_set = true;
    }

    prep_weights<<<CRr + KKG, 64>>>(v_reduce, g_reduce, b_reduce,
                                    bn_gamma, bn_beta, bn_mean, bn_var,
                                    v_span, g_span, b_span);

    // reduce: M=64, K=256, relu
    gemm_bias<CRr, Cc, true><<<dim3(HW / 64, 1, Bb), 256>>>(wr, br, x, r);

    // fused span + involution
    fused_kernel<<<dim3(Ww / TS, Hh / TS, Bb * Gg), 256, SMEM_FL * sizeof(float)>>>(x, r, out);
}

// round 4
// speedup vs baseline: 1.8129x; 1.3787x over previous
#include <cuda_runtime.h>
#include <math.h>
#include <stdint.h>

#define Bb   8
#define Cc   256
#define Hh   64
#define Ww   64
#define Gg   16
#define Dd   16
#define Pp   3
#define CRr  64
#define NT   49
#define KKG  784
#define HW   4096
#define EPSf 1e-5f

// ---------------- packed f32x2 helpers ---------------------------------------
typedef unsigned long long ull;
#define FMA2(acc, a, b) asm("fma.rn.f32x2 %0, %1, %2, %0;" : "+l"(acc) : "l"(a), "l"(b))
#define ADD2(acc, a)    asm("add.rn.f32x2 %0, %0, %1;"     : "+l"(acc) : "l"(a))
#define PACK2(d, lo, hi) asm("mov.b64 %0, {%1, %2};" : "=l"(d) : "f"(lo), "f"(hi))
#define UNPACK2(lo, hi, s) asm("mov.b64 {%0, %1}, %2;" : "=f"(lo), "=f"(hi) : "l"(s))
#define LDSV2(lo, hi, addr) \
    asm volatile("ld.shared.v2.u64 {%0, %1}, [%2];" : "=l"(lo), "=l"(hi) : "r"(addr))
#define STSV2(addr, lo, hi) \
    asm volatile("st.shared.v2.u64 [%0], {%1, %2};" :: "r"(addr), "l"(lo), "l"(hi))

static __device__ __forceinline__ uint32_t saddr(const void* p) {
    return (uint32_t)__cvta_generic_to_shared(p);
}

// ---------------- device-global scratch --------------------------------------
__device__ float g_wrT[Cc * CRr];                    // reduce weights [k][m]
__device__ float g_br[CRr];
__device__ __align__(16) float g_ws4[Gg * 32 * 56 * 4]; // [g][k/2][tap]{wk,wk,wk1,wk1}
__device__ float g_bsp[KKG];
__device__ float g_r[(size_t)Bb * CRr * HW];         // reduce output (8 MB) [b][c][hw]

// ---------------- weight preparation -----------------------------------------
__global__ void prep_weights(const float* __restrict__ v_reduce,
                             const float* __restrict__ g_reduce,
                             const float* __restrict__ b_reduce,
                             const float* __restrict__ bn_gamma,
                             const float* __restrict__ bn_beta,
                             const float* __restrict__ bn_mean,
                             const float* __restrict__ bn_var,
                             const float* __restrict__ v_span,
                             const float* __restrict__ g_span,
                             const float* __restrict__ b_span) {
    __shared__ float red[64];
    int row = blockIdx.x;
    int t = threadIdx.x;
    if (row < CRr) {
        float s = 0.f;
        for (int c = t; c < Cc; c += 64) {
            float v = v_reduce[row * Cc + c];
            s += v * v;
        }
        red[t] = s; __syncthreads();
        for (int off = 32; off > 0; off >>= 1) {
            if (t < off) red[t] += red[t + off];
            __syncthreads();
        }
        float nrm   = sqrtf(red[0]);
        float scale = bn_gamma[row] * rsqrtf(bn_var[row] + EPSf);
        float wmul  = g_reduce[row] / nrm * scale;
        for (int c = t; c < Cc; c += 64)
            g_wrT[c * CRr + row] = v_reduce[row * Cc + c] * wmul;
        if (t == 0)
            g_br[row] = (b_reduce[row] - bn_mean[row]) * scale + bn_beta[row];
    } else if (row < CRr + KKG) {
        int o = row - CRr;            // o = tap*16 + g
        int tap = o >> 4;
        int gq  = o & 15;
        float v0 = v_span[o * CRr + t];
        red[t] = v0 * v0; __syncthreads();
        for (int off = 32; off > 0; off >>= 1) {
            if (t < off) red[t] += red[t + off];
            __syncthreads();
        }
        float wmul = g_span[o] / sqrtf(red[0]);
        float w = v0 * wmul;
        int idx = ((gq * 32 + (t >> 1)) * 56 + tap) * 4 + (t & 1) * 2;
        g_ws4[idx]     = w;
        g_ws4[idx + 1] = w;
        if (t == 0) g_bsp[o] = b_span[o];
    } else {
        // zero-pad taps 49..55
        int p = row - (CRr + KKG);    // 0..111
        int gq = p / 7;
        int tap = NT + p % 7;
        int idx = ((gq * 32 + (t >> 1)) * 56 + tap) * 4 + (t & 1) * 2;
        g_ws4[idx]     = 0.f;
        g_ws4[idx + 1] = 0.f;
    }
}

// ---------------- reduce GEMM: m=64 (all) x n=256 px, FFMA2 -------------------
__global__ __launch_bounds__(256) void reduce_gemm(const float* __restrict__ x) {
    __shared__ float As[16][64];
    __shared__ float Bs[16][256];
    int b  = blockIdx.z;
    int n0 = blockIdx.x * 256;
    int tid = threadIdx.x;
    int ty = tid >> 5;          // m-octet 0..7
    int tx = tid & 31;          // px lane
    const float* xb = x + (size_t)b * Cc * HW;

    ull acc2[4][8];
#pragma unroll
    for (int i = 0; i < 4; i++)
#pragma unroll
        for (int j = 0; j < 8; j++) acc2[i][j] = 0ull;

    for (int k0 = 0; k0 < Cc; k0 += 16) {
        {
            int kr = tid >> 4, m4 = (tid & 15) * 4;
            *(float4*)&As[kr][m4] = *(const float4*)&g_wrT[(k0 + kr) * CRr + m4];
        }
#pragma unroll
        for (int q = 0; q < 4; q++) {
            int f = q * 256 + tid;
            int kr = f >> 6, c4 = (f & 63) * 4;
            *(float4*)&Bs[kr][c4] = *(const float4*)(xb + (size_t)(k0 + kr) * HW + n0 + c4);
        }
        __syncthreads();
#pragma unroll
        for (int k = 0; k < 16; k++) {
            ull a0, a1, a2, a3;
            LDSV2(a0, a1, saddr(&As[k][ty * 8]));
            LDSV2(a2, a3, saddr(&As[k][ty * 8 + 4]));
            float4 v0 = *(float4*)&Bs[k][tx * 4];
            float4 v1 = *(float4*)&Bs[k][128 + tx * 4];
            float bv[8] = {v0.x, v0.y, v0.z, v0.w, v1.x, v1.y, v1.z, v1.w};
            ull bd[8];
#pragma unroll
            for (int j = 0; j < 8; j++) PACK2(bd[j], bv[j], bv[j]);
            ull aa[4] = {a0, a1, a2, a3};
#pragma unroll
            for (int i = 0; i < 4; i++)
#pragma unroll
                for (int j = 0; j < 8; j++)
                    FMA2(acc2[i][j], aa[i], bd[j]);
        }
        __syncthreads();
    }

    // epilogue: bias + relu, store fp32 [b][m][hw]
    float bia[8];
#pragma unroll
    for (int i = 0; i < 8; i++) bia[i] = g_br[ty * 8 + i];
    float* rb = g_r + (size_t)b * CRr * HW;
#pragma unroll
    for (int i = 0; i < 4; i++) {
        float f[2][8];
#pragma unroll
        for (int j = 0; j < 8; j++) {
            float lo, hi;
            UNPACK2(lo, hi, acc2[i][j]);
            f[0][j] = fmaxf(lo + bia[2 * i], 0.f);
            f[1][j] = fmaxf(hi + bia[2 * i + 1], 0.f);
        }
#pragma unroll
        for (int h = 0; h < 2; h++) {
            int m = ty * 8 + 2 * i + h;
            *(float4*)(rb + (size_t)m * HW + n0 + tx * 4) =
                make_float4(f[h][0], f[h][1], f[h][2], f[h][3]);
            *(float4*)(rb + (size_t)m * HW + n0 + 128 + tx * 4) =
                make_float4(f[h][4], f[h][5], f[h][6], f[h][7]);
        }
    }
}

// ---------------- fused span + involution (FFMA2) -----------------------------
#define TS   16
#define XD   22
#define XSTR 20
#define KST  260      // ker row stride in floats
// byte offsets in dynamic smem (all 16B aligned)
#define OFF_RS   0                      // 64k x 256px fp32      = 65536 B
#define OFF_WS   65536                  // 32 x 56 x 16B         = 28672 B
#define OFF_XS   94208                  // 484 x 20 x 4          = 38720 B
#define OFF_KER  132928                 // 49 x 260 x 4          = 50960 B
#define OFF_BS   183888                 // 56 x 4                =   224 B
#define SMEM_REQ 184112

extern __shared__ char smraw[];

__global__ __launch_bounds__(256, 1) void fused_kernel(
        const float* __restrict__ x, float* __restrict__ out) {
    int tid  = threadIdx.x;
    int wid  = tid >> 5;
    int lane = tid & 31;
    int bz = blockIdx.z;
    int b = bz >> 4, g = bz & 15;
    int h0 = blockIdx.y * TS, w0 = blockIdx.x * TS;
    uint32_t sb = saddr(smraw);

    // ---- loads ---------------------------------------------------------------
    {   // rs: r tile [64c][256px]
        const float* rb = g_r + (size_t)b * CRr * HW;
        float* rs = (float*)(smraw + OFF_RS);
#pragma unroll
        for (int it = 0; it < 16; it++) {
            int i = tid + it * 256;
            int c = i >> 6, rem = i & 63;
            int y = rem >> 2, x4 = (rem & 3) << 2;
            float4 v = *(const float4*)(rb + (size_t)c * HW + (h0 + y) * Ww + w0 + x4);
            *(float4*)(rs + c * 256 + y * 16 + x4) = v;
        }
    }
    {   // ws4: 28672 B linear copy
        const uint4* src = (const uint4*)g_ws4 + (size_t)g * 1792;
        uint4* dst = (uint4*)(smraw + OFF_WS);
#pragma unroll
        for (int it = 0; it < 7; it++)
            dst[tid + it * 256] = src[tid + it * 256];
    }
    if (tid < 56)
        ((float*)(smraw + OFF_BS))[tid] = (tid < NT) ? g_bsp[tid * Gg + g] : 0.f;
    {   // x halo
        float* xs = (float*)(smraw + OFF_XS);
        const float* xbg = x + (size_t)(b * Cc + g * Dd) * HW;
        for (int idx = tid; idx < Dd * XD * XD; idx += 256) {
            int d  = idx / (XD * XD);
            int rr = idx - d * (XD * XD);
            int yy = rr / XD;
            int xx = rr - yy * XD;
            int gy = h0 + yy - Pp;
            int gx = w0 + xx - Pp;
            float v = 0.f;
            if (gy >= 0 && gy < Hh && gx >= 0 && gx < Ww)
                v = xbg[(size_t)d * HW + gy * Ww + gx];
            xs[(yy * XD + xx) * XSTR + d] = v;
        }
    }
    __syncthreads();

    // ---- phase 1: ker[tap][px] = sum_k ws[tap][k]*rs[k][px] + bias ------------
    {
        ull acc2[7][4];
#pragma unroll
        for (int i = 0; i < 7; i++)
#pragma unroll
            for (int p = 0; p < 4; p++) acc2[i][p] = 0ull;

        uint32_t rs_a = sb + OFF_RS + lane * 16;
        uint32_t ws_a = sb + OFF_WS + wid * 7 * 16;
#pragma unroll 1
        for (int k2 = 0; k2 < 32; k2++) {
            ull b0, b1, b2, b3, c0, c1, c2, c3;
            uint32_t ra = rs_a + k2 * 2048;
            LDSV2(b0, b1, ra);
            LDSV2(b2, b3, ra + 512);
            LDSV2(c0, c1, ra + 1024);
            LDSV2(c2, c3, ra + 1536);
            uint32_t wa = ws_a + k2 * 896;
#pragma unroll
            for (int i = 0; i < 7; i++) {
                ull a0, a1;
                LDSV2(a0, a1, wa + i * 16);
                FMA2(acc2[i][0], a0, b0);
                FMA2(acc2[i][1], a0, b1);
                FMA2(acc2[i][2], a0, b2);
                FMA2(acc2[i][3], a0, b3);
                FMA2(acc2[i][0], a1, c0);
                FMA2(acc2[i][1], a1, c1);
                FMA2(acc2[i][2], a1, c2);
                FMA2(acc2[i][3], a1, c3);
            }
        }
        // bias + store to ker smem (taps >= 49 discarded; warp 7 computes padding)
        float* bs = (float*)(smraw + OFF_BS);
#pragma unroll
        for (int i = 0; i < 7; i++) {
            int tap = wid * 7 + i;
            if (tap < NT) {
                ull bp;
                float bv = bs[tap];
                PACK2(bp, bv, bv);
#pragma unroll
                for (int p = 0; p < 4; p++) ADD2(acc2[i][p], bp);
                uint32_t ka = sb + OFF_KER + tap * (KST * 4) + lane * 16;
                STSV2(ka, acc2[i][0], acc2[i][1]);
                STSV2(ka + 512, acc2[i][2], acc2[i][3]);
            }
        }
    }
    __syncthreads();

    // ---- phase 2: involution ---------------------------------------------------
    {
        float* kerp = (float*)(smraw + OFF_KER);
        int pg = tid >> 2;
        int dq = tid & 3;
        int p0 = pg * 4;
        int y  = p0 >> 4;
        int x0 = p0 & 15;
        int d0 = dq * 4;

        ull acc2[2][4];   // [d-pair][px]
#pragma unroll
        for (int dp = 0; dp < 2; dp++)
#pragma unroll
            for (int px = 0; px < 4; px++) acc2[dp][px] = 0ull;

        uint32_t xs_a = sb + OFF_XS;
#pragma unroll
        for (int ki = 0; ki < 7; ki++) {
            uint32_t xrow = xs_a + (((y + ki) * XD + x0) * XSTR + d0) * 4;
            ull cur[4][2];
#pragma unroll
            for (int p = 0; p < 3; p++)
                LDSV2(cur[p][0], cur[p][1], xrow + p * 80);
#pragma unroll
            for (int kj = 0; kj < 7; kj++) {
                {
                    int s = (kj + 3) & 3;
                    LDSV2(cur[s][0], cur[s][1], xrow + (kj + 3) * 80);
                }
                float4 kv = *(float4*)(kerp + (ki * 7 + kj) * KST + p0);
                float kvv[4] = {kv.x, kv.y, kv.z, kv.w};
                ull kd[4];
#pragma unroll
                for (int px = 0; px < 4; px++) PACK2(kd[px], kvv[px], kvv[px]);
#pragma unroll
                for (int px = 0; px < 4; px++) {
                    int s = (kj + px) & 3;
                    FMA2(acc2[0][px], cur[s][0], kd[px]);
                    FMA2(acc2[1][px], cur[s][1], kd[px]);
                }
            }
        }

        // store: unpack d-pairs -> float4 over px per d
        float* ob = out + (size_t)(b * Cc + g * Dd + d0) * HW + (h0 + y) * Ww + w0 + x0;
#pragma unroll
        for (int dp = 0; dp < 2; dp++) {
            float lo[4], hi[4];
#pragma unroll
            for (int px = 0; px < 4; px++) UNPACK2(lo[px], hi[px], acc2[dp][px]);
            *(float4*)(ob + (size_t)(2 * dp) * HW)     = make_float4(lo[0], lo[1], lo[2], lo[3]);
            *(float4*)(ob + (size_t)(2 * dp + 1) * HW) = make_float4(hi[0], hi[1], hi[2], hi[3]);
        }
    }
}

// ---------------- launcher -----------------------------------------------------
extern "C" void kernel_launch(void* const* d_in, const int* in_sizes, int n_in,
                              void* d_out, int out_size) {
    const float* x        = (const float*)d_in[0];
    const float* v_reduce = (const float*)d_in[1];
    const float* g_reduce = (const float*)d_in[2];
    const float* b_reduce = (const float*)d_in[3];
    const float* bn_gamma = (const float*)d_in[4];
    const float* bn_beta  = (const float*)d_in[5];
    const float* bn_mean  = (const float*)d_in[6];
    const float* bn_var   = (const float*)d_in[7];
    const float* v_span   = (const float*)d_in[8];
    const float* g_span   = (const float*)d_in[9];
    const float* b_span   = (const float*)d_in[10];
    float* out = (float*)d_out;

    static bool attr_set = false;
    if (!attr_set) {
        cudaFuncSetAttribute(fused_kernel,
                             cudaFuncAttributeMaxDynamicSharedMemorySize, SMEM_REQ);
        attr_set = true;
    }

    prep_weights<<<CRr + KKG + Gg * 7, 64>>>(v_reduce, g_reduce, b_reduce,
                                             bn_gamma, bn_beta, bn_mean, bn_var,
                                             v_span, g_span, b_span);

    reduce_gemm<<<dim3(HW / 256, 1, Bb), 256>>>(x);

    fused_kernel<<<dim3(Ww / TS, Hh / TS, Bb * Gg), 256, SMEM_REQ>>>(x, out);
}